// round 16
// baseline (speedup 1.0000x reference)
#include <cuda_runtime.h>
#include <cuda_bf16.h>
#include <cstdint>

// ---------------- constants ----------------
#define HN     256
#define WN     256
#define HPAD   258
#define WPAD   258
#define NPTS   100000
#define BATCH  4
#define TOTPTS 400000
#define PLANE_PAD (HPAD*WPAD)                        // 66564
#define GRID_ELEMS ((size_t)BATCH*64*HPAD*WPAD)      // 17,040,384

// ---------------- device scratch ----------------
__device__ float g_bev[GRID_ELEMS];                  // fp32 NHWC padded (scatter target)
__device__ __nv_bfloat16 g_c2h[GRID_ELEMS];          // conv2 input NHWC padded, hi
__device__ __nv_bfloat16 g_c2l[GRID_ELEMS];          // lo
__device__ __nv_bfloat16 g_cw1h[9*64*64];            // [tap][co][ci] bf16 hi, BN-folded
__device__ __nv_bfloat16 g_cw1l[9*64*64];
__device__ __nv_bfloat16 g_cw2h[9*64*64];
__device__ __nv_bfloat16 g_cw2l[9*64*64];
__device__ __nv_bfloat16 g_mw1h[2*64*64];            // MLP L1 W [panel][co][k] hi (k<128)
__device__ __nv_bfloat16 g_mw1l[2*64*64];
__device__ __nv_bfloat16 g_mw2h[64*64];              // MLP L2 W [co][c]
__device__ __nv_bfloat16 g_mw2l[64*64];
__device__ float g_w1p[3*64];                        // pos rows of W1 (BN-folded, fp32)
__device__ float g_fb1[64];
__device__ float g_cb1[64];
__device__ float g_cb2[64];

// ---------------- mma / ldmatrix / cp.async helpers ----------------
__device__ __forceinline__ uint32_t smem_u32(const void* p){
    uint32_t a;
    asm("{ .reg .u64 t; cvta.to.shared.u64 t, %1; cvt.u32.u64 %0, t; }"
        : "=r"(a) : "l"(p));
    return a;
}
#define LDSM_X4(r0,r1,r2,r3,addr) asm volatile( \
    "ldmatrix.sync.aligned.m8n8.x4.shared.b16 {%0,%1,%2,%3}, [%4];" \
    : "=r"(r0), "=r"(r1), "=r"(r2), "=r"(r3) : "r"(addr))
#define LDSM_X2(r0,r1,addr) asm volatile( \
    "ldmatrix.sync.aligned.m8n8.x2.shared.b16 {%0,%1}, [%2];" \
    : "=r"(r0), "=r"(r1) : "r"(addr))
#define MMA_BF16(c0,c1,c2,c3,a0,a1,a2,a3,b0,b1) asm volatile( \
    "mma.sync.aligned.m16n8k16.row.col.f32.bf16.bf16.f32 " \
    "{%0,%1,%2,%3}, {%4,%5,%6,%7}, {%8,%9}, {%0,%1,%2,%3};" \
    : "+f"(c0), "+f"(c1), "+f"(c2), "+f"(c3) \
    : "r"(a0), "r"(a1), "r"(a2), "r"(a3), "r"(b0), "r"(b1))
#define CP16(dst, src) asm volatile( \
    "cp.async.cg.shared.global [%0], [%1], 16;" :: "r"(dst), "l"(src))
#define CP_COMMIT() asm volatile("cp.async.commit_group;" ::: "memory")
#define CP_WAIT(n)  asm volatile("cp.async.wait_group %0;" :: "n"(n) : "memory")

// bf16x2 hi/lo split of two fp32 values (rn residual split)
__device__ __forceinline__ void split2(float v0, float v1,
                                       uint32_t& hp, uint32_t& lp){
    __nv_bfloat16 h0 = __float2bfloat16(v0);
    __nv_bfloat16 h1 = __float2bfloat16(v1);
    __nv_bfloat16 l0 = __float2bfloat16(v0 - __bfloat162float(h0));
    __nv_bfloat16 l1 = __float2bfloat16(v1 - __bfloat162float(h1));
    hp = (uint32_t)__bfloat16_as_ushort(h0) |
         ((uint32_t)__bfloat16_as_ushort(h1) << 16);
    lp = (uint32_t)__bfloat16_as_ushort(l0) |
         ((uint32_t)__bfloat16_as_ushort(l1) << 16);
}

// ---------------- init: zero BEV grid + fold weights (one launch) ----------------
#define ZBLOCKS 16641    // ceil(GRID_ELEMS/4 / 256)
#define PREP_TOTAL (8192 + 4096 + 192 + 64 + 2*9*64*64 + 2*64)

__global__ void init_kernel(
    const float* __restrict__ w1, const float* __restrict__ b1,
    const float* __restrict__ g1, const float* __restrict__ be1,
    const float* __restrict__ m1, const float* __restrict__ v1,
    const float* __restrict__ w2,
    const float* __restrict__ cw1, const float* __restrict__ cb1,
    const float* __restrict__ cg1, const float* __restrict__ cbe1,
    const float* __restrict__ cm1, const float* __restrict__ cv1,
    const float* __restrict__ cw2, const float* __restrict__ cb2,
    const float* __restrict__ cg2, const float* __restrict__ cbe2,
    const float* __restrict__ cm2, const float* __restrict__ cv2)
{
    if (blockIdx.x < ZBLOCKS){
        size_t i = (size_t)blockIdx.x*256 + threadIdx.x;
        if (i < GRID_ELEMS/4)
            ((float4*)g_bev)[i] = make_float4(0.f,0.f,0.f,0.f);
        return;
    }
    int idx = (blockIdx.x - ZBLOCKS)*256 + threadIdx.x;
    if (idx >= PREP_TOTAL) return;
    if (idx < 8192){                      // MLP W1 k<128: [panel][co][kk]
        int p = idx >> 12, r = idx & 4095, co = r >> 6, kk = r & 63;
        int k = p*64 + kk;
        float s = g1[co]*rsqrtf(v1[co]+1e-5f);
        float wf = w1[k*64+co]*s;
        __nv_bfloat16 hi = __float2bfloat16(wf);
        g_mw1h[idx] = hi;
        g_mw1l[idx] = __float2bfloat16(wf - __bfloat162float(hi));
        return;
    }
    idx -= 8192;
    if (idx < 4096){                      // MLP W2: [co][c]
        int co = idx >> 6, c = idx & 63;
        float wf = w2[c*64+co];
        __nv_bfloat16 hi = __float2bfloat16(wf);
        g_mw2h[idx] = hi;
        g_mw2l[idx] = __float2bfloat16(wf - __bfloat162float(hi));
        return;
    }
    idx -= 4096;
    if (idx < 192){                       // pos rows of W1, fp32
        int i = idx >> 6, co = idx & 63;
        float s = g1[co]*rsqrtf(v1[co]+1e-5f);
        g_w1p[idx] = w1[(128+i)*64+co]*s;
        return;
    }
    idx -= 192;
    if (idx < 64){
        float s = g1[idx]*rsqrtf(v1[idx]+1e-5f);
        g_fb1[idx] = (b1[idx]-m1[idx])*s + be1[idx];
        return;
    }
    idx -= 64;
    if (idx < 9*64*64){
        int t = idx >> 12, co = (idx >> 6) & 63, ci = idx & 63;
        float s = cg1[co]*rsqrtf(cv1[co]+1e-5f);
        float wf = cw1[(co*64+ci)*9 + t]*s;
        __nv_bfloat16 hi = __float2bfloat16(wf);
        g_cw1h[idx] = hi;
        g_cw1l[idx] = __float2bfloat16(wf - __bfloat162float(hi));
        return;
    }
    idx -= 9*64*64;
    if (idx < 9*64*64){
        int t = idx >> 12, co = (idx >> 6) & 63, ci = idx & 63;
        float s = cg2[co]*rsqrtf(cv2[co]+1e-5f);
        float wf = cw2[(co*64+ci)*9 + t]*s;
        __nv_bfloat16 hi = __float2bfloat16(wf);
        g_cw2h[idx] = hi;
        g_cw2l[idx] = __float2bfloat16(wf - __bfloat162float(hi));
        return;
    }
    idx -= 9*64*64;
    if (idx < 64){
        float s = cg1[idx]*rsqrtf(cv1[idx]+1e-5f);
        g_cb1[idx] = (cb1[idx]-cm1[idx])*s + cbe1[idx];
        return;
    }
    idx -= 64;
    if (idx < 64){
        float s = cg2[idx]*rsqrtf(cv2[idx]+1e-5f);
        g_cb2[idx] = (cb2[idx]-cm2[idx])*s + cbe2[idx];
    }
}

// ---------------- tensor-core MLP + scatter-max (R13, proven) ----------------
#define MLPS_W1   0
#define MLPS_W2   32768
#define MLPS_A    49152
#define MLPS_HH   81920
#define MLPS_HL   90112
#define MLPS_W1P  98304
#define MLPS_FB1  99072
#define MLPS_B2   99328
#define MLPS_POS  99584      // 2 x 64 x 4 floats
#define MLPS_INFO 101632     // 2 x 64 ints
#define MLP_SMEM_BYTES 102144
#define NCHUNKS 6250

__global__ __launch_bounds__(256, 2)
void mlp_mma_kernel(const float* __restrict__ points,
                    const float* __restrict__ features,
                    const float* __restrict__ b2)
{
    extern __shared__ char smem[];
    uint32_t sb = smem_u32(smem);
    float* s_w1p = (float*)(smem + MLPS_W1P);
    float* s_fb1 = (float*)(smem + MLPS_FB1);
    float* s_b2  = (float*)(smem + MLPS_B2);

    int tid = threadIdx.x;
    int lane = tid & 31;
    int wq = tid >> 5;
    int wm = wq & 3;
    int wn = wq >> 2;
    int tile = lane >> 3;
    int r16  = ((tile & 1) << 3) + (lane & 7);
    int kcA  = tile >> 1;
    int coL  = lane & 7;
    int kcB  = tile & 1;

    for (int j = tid; j < 2048; j += 256){
        int panel = j >> 9, r = (j >> 3) & 63, c = j & 7;
        const __nv_bfloat16* src = (panel < 2)
            ? (g_mw1h + panel*4096 + r*64 + c*8)
            : (g_mw1l + (panel-2)*4096 + r*64 + c*8);
        CP16(sb + MLPS_W1 + panel*8192 + r*128 + ((c ^ (r & 7)) << 4), src);
    }
    for (int j = tid; j < 1024; j += 256){
        int panel = j >> 9, r = (j >> 3) & 63, c = j & 7;
        const __nv_bfloat16* src = (panel ? g_mw2l : g_mw2h) + r*64 + c*8;
        CP16(sb + MLPS_W2 + panel*8192 + r*128 + ((c ^ (r & 7)) << 4), src);
    }
    CP_COMMIT();
    if (tid < 192) s_w1p[tid] = g_w1p[tid];
    if (tid < 64){ s_fb1[tid] = g_fb1[tid]; s_b2[tid] = b2[tid]; }
    CP_WAIT(0);
    __syncthreads();

    int par = 0;
    for (int chunk = blockIdx.x; chunk < NCHUNKS; chunk += gridDim.x, par ^= 1){
        int g0 = chunk * 64;
        float* s_pos = (float*)(smem + MLPS_POS) + par*256;
        int*   s_info= (int*)(smem + MLPS_INFO) + par*64;

        // ---- stage A: issue ALL 8 feature loads first, then convert ----
        uint4 u[8];
        {
            #pragma unroll
            for (int i = 0; i < 4; ++i){
                int j = tid + i*256;
                int pt = j >> 4, oct = j & 15;
                const uint4* src =
                    (const uint4*)(features + (size_t)(g0+pt)*128 + oct*8);
                u[2*i]   = src[0];
                u[2*i+1] = src[1];
            }
            float px_ = 0.f, py_ = 0.f, pz_ = 0.f; int info = -1;
            if (tid < 64){
                int g = g0 + tid;
                float x = points[(size_t)g*3+0];
                float y = points[(size_t)g*3+1];
                float z = points[(size_t)g*3+2];
                bool valid = (x >= -50.f) && (x < 50.f) && (y >= -50.f) &&
                             (y < 50.f) && (z >= -3.f) && (z < 5.f);
                px_ = __fdiv_rn(x + 50.f, 100.f);
                py_ = __fdiv_rn(y + 50.f, 100.f);
                pz_ = __fdiv_rn(z + 3.f, 8.f);
                if (valid){
                    int col = (int)__fdiv_rn(x + 50.f, 0.390625f);
                    int row = (int)__fdiv_rn(y + 50.f, 0.390625f);
                    col = min(max(col,0),255); row = min(max(row,0),255);
                    int b = g / NPTS;
                    info = (b<<18) | (row<<9) | col;
                }
            }
            #pragma unroll
            for (int i = 0; i < 4; ++i){
                int j = tid + i*256;
                int pt = j >> 4, oct = j & 15;
                uint4 u0 = u[2*i], u1 = u[2*i+1];
                uint4 hv, lv;
                hv.x = __byte_perm(u0.x, u0.y, 0x7632);
                hv.y = __byte_perm(u0.z, u0.w, 0x7632);
                hv.z = __byte_perm(u1.x, u1.y, 0x7632);
                hv.w = __byte_perm(u1.z, u1.w, 0x7632);
                float l0 = __uint_as_float(u0.x) - __uint_as_float(u0.x & 0xFFFF0000u);
                float l1 = __uint_as_float(u0.y) - __uint_as_float(u0.y & 0xFFFF0000u);
                float l2 = __uint_as_float(u0.z) - __uint_as_float(u0.z & 0xFFFF0000u);
                float l3 = __uint_as_float(u0.w) - __uint_as_float(u0.w & 0xFFFF0000u);
                float l4 = __uint_as_float(u1.x) - __uint_as_float(u1.x & 0xFFFF0000u);
                float l5 = __uint_as_float(u1.y) - __uint_as_float(u1.y & 0xFFFF0000u);
                float l6 = __uint_as_float(u1.z) - __uint_as_float(u1.z & 0xFFFF0000u);
                float l7 = __uint_as_float(u1.w) - __uint_as_float(u1.w & 0xFFFF0000u);
                lv.x = __byte_perm(__float_as_uint(l0), __float_as_uint(l1), 0x7632);
                lv.y = __byte_perm(__float_as_uint(l2), __float_as_uint(l3), 0x7632);
                lv.z = __byte_perm(__float_as_uint(l4), __float_as_uint(l5), 0x7632);
                lv.w = __byte_perm(__float_as_uint(l6), __float_as_uint(l7), 0x7632);
                int panel = oct >> 3, c = oct & 7;
                uint32_t off = MLPS_A + panel*8192 + pt*128 + ((c ^ (pt & 7)) << 4);
                *(uint4*)(smem + off) = hv;
                *(uint4*)(smem + off + 16384) = lv;
            }
            if (tid < 64){
                s_pos[tid*4+0] = px_;
                s_pos[tid*4+1] = py_;
                s_pos[tid*4+2] = pz_;
                s_info[tid] = info;
            }
        }
        __syncthreads();                     // S1

        // ---- layer 1 GEMM ----
        float acc[4][4];
        #pragma unroll
        for (int in = 0; in < 4; ++in)
            #pragma unroll
            for (int r = 0; r < 4; ++r) acc[in][r] = 0.f;

        int arow = 16*wm + r16;
        #pragma unroll
        for (int ks = 0; ks < 8; ++ks){
            int panel = ks >> 2, cc = 2*(ks & 3);
            uint32_t ah[4], al[4], bh[4][2], bl[4][2];
            uint32_t aad = sb + MLPS_A + panel*8192 + arow*128
                         + (((cc + kcA) ^ (arow & 7)) << 4);
            LDSM_X4(ah[0], ah[1], ah[2], ah[3], aad);
            LDSM_X4(al[0], al[1], al[2], al[3], aad + 16384);
            #pragma unroll
            for (int in = 0; in < 4; ++in){
                int co = 32*wn + 8*in + coL;
                uint32_t bad = sb + MLPS_W1 + panel*8192 + co*128
                             + (((cc + kcB) ^ (co & 7)) << 4);
                LDSM_X2(bh[in][0], bh[in][1], bad);
                LDSM_X2(bl[in][0], bl[in][1], bad + 16384);
            }
            #pragma unroll
            for (int in = 0; in < 4; ++in){
                MMA_BF16(acc[in][0],acc[in][1],acc[in][2],acc[in][3],
                         ah[0],ah[1],ah[2],ah[3], bh[in][0],bh[in][1]);
                MMA_BF16(acc[in][0],acc[in][1],acc[in][2],acc[in][3],
                         ah[0],ah[1],ah[2],ah[3], bl[in][0],bl[in][1]);
                MMA_BF16(acc[in][0],acc[in][1],acc[in][2],acc[in][3],
                         al[0],al[1],al[2],al[3], bh[in][0],bh[in][1]);
            }
        }

        // ---- epilogue 1: + pos (fp32) + bias, ReLU, rn-split -> H ----
        int rb = 16*wm + (lane >> 2);
        int cb = 2*(lane & 3);
        #pragma unroll
        for (int in = 0; in < 4; ++in){
            int c0 = 32*wn + 8*in + cb;
            float p0a = s_w1p[c0],      p0b = s_w1p[c0+1];
            float p1a = s_w1p[64+c0],   p1b = s_w1p[64+c0+1];
            float p2a = s_w1p[128+c0],  p2b = s_w1p[128+c0+1];
            float fba = s_fb1[c0], fbb = s_fb1[c0+1];
            int ch = c0 >> 3;
            #pragma unroll
            for (int half = 0; half < 2; ++half){
                int pt = rb + 8*half;
                float px = s_pos[pt*4], py = s_pos[pt*4+1], pz = s_pos[pt*4+2];
                float v0 = acc[in][2*half]   + fba + px*p0a + py*p1a + pz*p2a;
                float v1 = acc[in][2*half+1] + fbb + px*p0b + py*p1b + pz*p2b;
                v0 = fmaxf(v0, 0.f); v1 = fmaxf(v1, 0.f);
                uint32_t hp, lp;
                split2(v0, v1, hp, lp);
                uint32_t off = pt*128 + ((ch ^ (pt & 7)) << 4) + cb*2;
                *(uint32_t*)(smem + MLPS_HH + off) = hp;
                *(uint32_t*)(smem + MLPS_HL + off) = lp;
            }
        }
        __syncthreads();                     // S2

        // ---- layer 2 GEMM ----
        float acc2[4][4];
        #pragma unroll
        for (int in = 0; in < 4; ++in)
            #pragma unroll
            for (int r = 0; r < 4; ++r) acc2[in][r] = 0.f;

        #pragma unroll
        for (int ks = 0; ks < 4; ++ks){
            int cc = 2*ks;
            uint32_t ah[4], al[4], bh[4][2], bl[4][2];
            uint32_t aad = sb + MLPS_HH + arow*128
                         + (((cc + kcA) ^ (arow & 7)) << 4);
            LDSM_X4(ah[0], ah[1], ah[2], ah[3], aad);
            LDSM_X4(al[0], al[1], al[2], al[3], aad + 8192);
            #pragma unroll
            for (int in = 0; in < 4; ++in){
                int co = 32*wn + 8*in + coL;
                uint32_t bad = sb + MLPS_W2 + co*128
                             + (((cc + kcB) ^ (co & 7)) << 4);
                LDSM_X2(bh[in][0], bh[in][1], bad);
                LDSM_X2(bl[in][0], bl[in][1], bad + 8192);
            }
            #pragma unroll
            for (int in = 0; in < 4; ++in){
                MMA_BF16(acc2[in][0],acc2[in][1],acc2[in][2],acc2[in][3],
                         ah[0],ah[1],ah[2],ah[3], bh[in][0],bh[in][1]);
                MMA_BF16(acc2[in][0],acc2[in][1],acc2[in][2],acc2[in][3],
                         ah[0],ah[1],ah[2],ah[3], bl[in][0],bl[in][1]);
                MMA_BF16(acc2[in][0],acc2[in][1],acc2[in][2],acc2[in][3],
                         al[0],al[1],al[2],al[3], bh[in][0],bh[in][1]);
            }
        }

        // ---- epilogue 2: + b2, scatter-max (NHWC: adjacent channels) ----
        #pragma unroll
        for (int in = 0; in < 4; ++in){
            int c0 = 32*wn + 8*in + cb;
            float bb0 = s_b2[c0], bb1 = s_b2[c0+1];
            #pragma unroll
            for (int half = 0; half < 2; ++half){
                int pt = rb + 8*half;
                int info = s_info[pt];
                if (info < 0) continue;
                int b   = info >> 18;
                int row = (info >> 9) & 511;
                int col = info & 511;
                float v0 = acc2[in][2*half]   + bb0;
                float v1 = acc2[in][2*half+1] + bb1;
                size_t obase = (((size_t)b*HPAD + row + 1)*WPAD + col + 1)*64 + c0;
                if (v0 > 0.f)
                    atomicMax((unsigned int*)&g_bev[obase], __float_as_uint(v0));
                if (v1 > 0.f)
                    atomicMax((unsigned int*)&g_bev[obase + 1],
                              __float_as_uint(v1));
            }
        }
        // no end barrier: pos/info double-buffered; A/H protected by S1/S2
    }
}

// ---------------- tensor-core conv via mma.sync bf16 ----------------
// MODE 0: input = fp32 NHWC g_bev, staged via batched LDG + split2 + STS.
// MODE 1: input = bf16 hi/lo via cp.async. Out: MODE0 bf16 hi/lo, MODE1 fp32 NCHW.
#define SA_BUF   33280
#define SW_OFF   (2*SA_BUF)            // 66560
#define SW_BUF   16384
#define SBIAS    (SW_OFF + 2*SW_BUF)   // 99328
#define CONV_SMEM_BYTES (SBIAS + 256)  // 99584

template<int MODE>
__global__ __launch_bounds__(256, 2)
void conv_mma_kernel(const float* __restrict__ in_f,
                     const __nv_bfloat16* __restrict__ in_h,
                     const __nv_bfloat16* __restrict__ in_l,
                     const __nv_bfloat16* __restrict__ w_h,
                     const __nv_bfloat16* __restrict__ w_l,
                     const float* __restrict__ bias,
                     __nv_bfloat16* __restrict__ out_h,
                     __nv_bfloat16* __restrict__ out_l,
                     float* __restrict__ out_f)
{
    extern __shared__ char smem[];
    uint32_t sbase = smem_u32(smem);
    float* s_bias = (float*)(smem + SBIAS);

    int tid = threadIdx.x;
    int lane = tid & 31;
    int wq = tid >> 5;
    int wm = wq & 3;
    int wn = wq >> 2;
    int b = blockIdx.z, h = blockIdx.y, W0 = blockIdx.x * 128;

    if (tid < 64) s_bias[tid] = bias[tid];

    int tile = lane >> 3;
    int r16  = ((tile & 1) << 3) + (lane & 7);
    int kcA  = tile >> 1;
    int coL  = (lane & 7);
    int kcB  = tile & 1;

    // MODE 1: cp.async strip staging (bf16 hi/lo inputs)
    auto stage_strip_async = [&](int dh, int buf){
        const char* srch = (const char*)(in_h +
            (((size_t)b*HPAD + h + dh)*WPAD + W0)*64);
        const char* srcl = (const char*)(in_l +
            (((size_t)b*HPAD + h + dh)*WPAD + W0)*64);
        uint32_t dsth = sbase + buf*SA_BUF;
        uint32_t dstl = dsth + 16640;
        #pragma unroll 1
        for (int ch = tid; ch < 1040; ch += 256){
            int px = ch >> 3, c = ch & 7;
            uint32_t off = px*128 + ((c ^ (px & 7)) << 4);
            CP16(dsth + off, srch + ch*16);
            CP16(dstl + off, srcl + ch*16);
        }
    };
    // MODE 0: batched LDG fp32 (all loads first) -> split2 -> STS
    auto stage_strip_f32 = [&](int dh, int buf){
        const float* src = in_f + (((size_t)b*HPAD + h + dh)*WPAD + W0)*64;
        char* dsth = smem + buf*SA_BUF;
        char* dstl = dsth + 16640;
        float4 f[10];
        #pragma unroll
        for (int it = 0; it < 5; ++it){
            int ch = tid + it*256;
            if (ch < 1040){
                const float4* s4 = (const float4*)(src + (ch>>3)*64 + (ch&7)*8);
                f[2*it]   = s4[0];
                f[2*it+1] = s4[1];
            }
        }
        #pragma unroll
        for (int it = 0; it < 5; ++it){
            int ch = tid + it*256;
            if (ch < 1040){
                int px = ch >> 3, c = ch & 7;
                uint4 hv, lv;
                split2(f[2*it].x,   f[2*it].y,   hv.x, lv.x);
                split2(f[2*it].z,   f[2*it].w,   hv.y, lv.y);
                split2(f[2*it+1].x, f[2*it+1].y, hv.z, lv.z);
                split2(f[2*it+1].z, f[2*it+1].w, hv.w, lv.w);
                uint32_t off = px*128 + ((c ^ (px & 7)) << 4);
                *(uint4*)(dsth + off) = hv;
                *(uint4*)(dstl + off) = lv;
            }
        }
    };
    auto stage_strip = [&](int dh, int buf){
        if (MODE == 0) stage_strip_f32(dh, buf);
        else           stage_strip_async(dh, buf);
    };
    auto stage_w = [&](int t, int buf){
        const char* srch = (const char*)(w_h + t*4096);
        const char* srcl = (const char*)(w_l + t*4096);
        uint32_t dsth = sbase + SW_OFF + buf*SW_BUF;
        uint32_t dstl = dsth + 8192;
        #pragma unroll 1
        for (int ch = tid; ch < 512; ch += 256){
            int co = ch >> 3, c = ch & 7;
            uint32_t off = co*128 + ((c ^ (co & 7)) << 4);
            CP16(dsth + off, srch + ch*16);
            CP16(dstl + off, srcl + ch*16);
        }
    };

    float acc[2][4][4];
    #pragma unroll
    for (int im = 0; im < 2; ++im)
        #pragma unroll
        for (int in = 0; in < 4; ++in)
            #pragma unroll
            for (int r = 0; r < 4; ++r) acc[im][in][r] = 0.f;

    stage_w(0, 0);
    stage_strip(0, 0);
    CP_COMMIT();

    #pragma unroll 1
    for (int t = 0; t < 9; ++t){
        int dh = t / 3, dw = t - dh*3;
        if (t < 8){
            stage_w(t+1, (t+1) & 1);
            if ((t+1) % 3 == 0) stage_strip((t+1)/3, ((t+1)/3) & 1);
            CP_COMMIT();
            CP_WAIT(1);
        } else {
            CP_WAIT(0);
        }
        __syncthreads();

        uint32_t Ah = sbase + (dh & 1)*SA_BUF;
        uint32_t Al = Ah + 16640;
        uint32_t Wh = sbase + SW_OFF + (t & 1)*SW_BUF;
        uint32_t Wl = Wh + 8192;

        #pragma unroll
        for (int ks = 0; ks < 4; ++ks){
            uint32_t ah[2][4], al[2][4], bh[4][2], bl[4][2];
            #pragma unroll
            for (int im = 0; im < 2; ++im){
                int px = dw + 32*wm + 16*im + r16;
                int chunk = 2*ks + kcA;
                uint32_t ad = Ah + px*128 + ((chunk ^ (px & 7)) << 4);
                LDSM_X4(ah[im][0], ah[im][1], ah[im][2], ah[im][3], ad);
            }
            #pragma unroll
            for (int in = 0; in < 4; ++in){
                int co = 32*wn + 8*in + coL;
                int chunk = 2*ks + kcB;
                uint32_t bd = Wh + co*128 + ((chunk ^ (co & 7)) << 4);
                LDSM_X2(bh[in][0], bh[in][1], bd);
            }
            #pragma unroll
            for (int im = 0; im < 2; ++im)
                #pragma unroll
                for (int in = 0; in < 4; ++in)
                    MMA_BF16(acc[im][in][0], acc[im][in][1],
                             acc[im][in][2], acc[im][in][3],
                             ah[im][0], ah[im][1], ah[im][2], ah[im][3],
                             bh[in][0], bh[in][1]);
            #pragma unroll
            for (int in = 0; in < 4; ++in){
                int co = 32*wn + 8*in + coL;
                int chunk = 2*ks + kcB;
                uint32_t bd = Wl + co*128 + ((chunk ^ (co & 7)) << 4);
                LDSM_X2(bl[in][0], bl[in][1], bd);
            }
            #pragma unroll
            for (int im = 0; im < 2; ++im)
                #pragma unroll
                for (int in = 0; in < 4; ++in)
                    MMA_BF16(acc[im][in][0], acc[im][in][1],
                             acc[im][in][2], acc[im][in][3],
                             ah[im][0], ah[im][1], ah[im][2], ah[im][3],
                             bl[in][0], bl[in][1]);
            #pragma unroll
            for (int im = 0; im < 2; ++im){
                int px = dw + 32*wm + 16*im + r16;
                int chunk = 2*ks + kcA;
                uint32_t ad = Al + px*128 + ((chunk ^ (px & 7)) << 4);
                LDSM_X4(al[im][0], al[im][1], al[im][2], al[im][3], ad);
            }
            #pragma unroll
            for (int im = 0; im < 2; ++im)
                #pragma unroll
                for (int in = 0; in < 4; ++in)
                    MMA_BF16(acc[im][in][0], acc[im][in][1],
                             acc[im][in][2], acc[im][in][3],
                             al[im][0], al[im][1], al[im][2], al[im][3],
                             bh[in][0], bh[in][1]);
        }
        __syncthreads();
    }

    int rbase = 32*wm + (lane >> 2);
    int cbase = 32*wn + 2*(lane & 3);
    #pragma unroll
    for (int im = 0; im < 2; ++im){
        #pragma unroll
        for (int in = 0; in < 4; ++in){
            int c0 = cbase + 8*in;
            float bia = s_bias[c0], bib = s_bias[c0+1];
            #pragma unroll
            for (int half = 0; half < 2; ++half){
                int px = rbase + 16*im + 8*half;
                float v0 = fmaxf(acc[im][in][2*half]   + bia, 0.f);
                float v1 = fmaxf(acc[im][in][2*half+1] + bib, 0.f);
                if (MODE == 0){
                    uint32_t hp, lp;
                    split2(v0, v1, hp, lp);
                    size_t e = (((size_t)b*HPAD + h + 1)*WPAD + (W0 + px + 1))*64 + c0;
                    *(uint32_t*)(out_h + e) = hp;
                    *(uint32_t*)(out_l + e) = lp;
                } else {
                    size_t e = ((size_t)(b*64 + c0)*HN + h)*WN + W0 + px;
                    out_f[e] = v0;
                    out_f[e + (size_t)HN*WN] = v1;
                }
            }
        }
    }
}

// ---------------- launch ----------------
extern "C" void kernel_launch(void* const* d_in, const int* in_sizes, int n_in,
                              void* d_out, int out_size)
{
    const float* points   = (const float*)d_in[0];
    const float* features = (const float*)d_in[1];
    const float* w1   = (const float*)d_in[2];
    const float* b1   = (const float*)d_in[3];
    const float* g1   = (const float*)d_in[4];
    const float* be1  = (const float*)d_in[5];
    const float* m1   = (const float*)d_in[6];
    const float* v1   = (const float*)d_in[7];
    const float* w2   = (const float*)d_in[8];
    const float* b2   = (const float*)d_in[9];
    const float* cw1  = (const float*)d_in[10];
    const float* cb1  = (const float*)d_in[11];
    const float* cg1  = (const float*)d_in[12];
    const float* cbe1 = (const float*)d_in[13];
    const float* cm1  = (const float*)d_in[14];
    const float* cv1  = (const float*)d_in[15];
    const float* cw2  = (const float*)d_in[16];
    const float* cb2  = (const float*)d_in[17];
    const float* cg2  = (const float*)d_in[18];
    const float* cbe2 = (const float*)d_in[19];
    const float* cm2  = (const float*)d_in[20];
    const float* cv2  = (const float*)d_in[21];
    float* out = (float*)d_out;

    void *p_bev, *p_c2h, *p_c2l;
    void *p_w1h, *p_w1l, *p_w2h, *p_w2l, *p_cb1, *p_cb2;
    cudaGetSymbolAddress(&p_bev, g_bev);
    cudaGetSymbolAddress(&p_c2h, g_c2h);
    cudaGetSymbolAddress(&p_c2l, g_c2l);
    cudaGetSymbolAddress(&p_w1h, g_cw1h);
    cudaGetSymbolAddress(&p_w1l, g_cw1l);
    cudaGetSymbolAddress(&p_w2h, g_cw2h);
    cudaGetSymbolAddress(&p_w2l, g_cw2l);
    cudaGetSymbolAddress(&p_cb1, g_cb1);
    cudaGetSymbolAddress(&p_cb2, g_cb2);

    cudaFuncSetAttribute(mlp_mma_kernel,
        cudaFuncAttributeMaxDynamicSharedMemorySize, MLP_SMEM_BYTES);
    cudaFuncSetAttribute(conv_mma_kernel<0>,
        cudaFuncAttributeMaxDynamicSharedMemorySize, CONV_SMEM_BYTES);
    cudaFuncSetAttribute(conv_mma_kernel<1>,
        cudaFuncAttributeMaxDynamicSharedMemorySize, CONV_SMEM_BYTES);

    // 1) zero BEV grid + fold weights (one launch)
    int prep_blocks = (PREP_TOTAL + 255)/256;
    init_kernel<<<ZBLOCKS + prep_blocks, 256>>>(
        w1,b1,g1,be1,m1,v1, w2,
        cw1,cb1,cg1,cbe1,cm1,cv1,
        cw2,cb2,cg2,cbe2,cm2,cv2);

    // 2) tensor-core point MLP + scatter-max (persistent, NHWC scatter)
    mlp_mma_kernel<<<296, 256, MLP_SMEM_BYTES>>>(points, features, b2);

    // 3) conv1 (mma.sync): fp32 g_bev -> g_c2 hi/lo (batched inline split)
    dim3 cgrid(2, HN, BATCH);
    conv_mma_kernel<0><<<cgrid, 256, CONV_SMEM_BYTES>>>(
        (const float*)p_bev, nullptr, nullptr,
        (const __nv_bfloat16*)p_w1h, (const __nv_bfloat16*)p_w1l,
        (const float*)p_cb1,
        (__nv_bfloat16*)p_c2h, (__nv_bfloat16*)p_c2l, nullptr);

    // 4) conv2 (mma.sync): g_c2 hi/lo -> d_out (NCHW fp32)
    conv_mma_kernel<1><<<cgrid, 256, CONV_SMEM_BYTES>>>(
        nullptr,
        (const __nv_bfloat16*)p_c2h, (const __nv_bfloat16*)p_c2l,
        (const __nv_bfloat16*)p_w2h, (const __nv_bfloat16*)p_w2l,
        (const float*)p_cb2,
        nullptr, nullptr, out);
}

// round 17
// speedup vs baseline: 1.5201x; 1.5201x over previous
#include <cuda_runtime.h>
#include <cuda_bf16.h>
#include <cstdint>

// ---------------- constants ----------------
#define HN     256
#define WN     256
#define HPAD   258
#define WPAD   258
#define NPTS   100000
#define BATCH  4
#define TOTPTS 400000
#define PLANE_PAD (HPAD*WPAD)                        // 66564
#define GRID_ELEMS ((size_t)BATCH*64*HPAD*WPAD)      // 17,040,384

// ---------------- device scratch ----------------
__device__ float g_bev[GRID_ELEMS];                  // fp32 NHWC padded (scatter target)
__device__ __nv_bfloat16 g_c2h[GRID_ELEMS];          // conv2 input NHWC padded, hi
__device__ __nv_bfloat16 g_c2l[GRID_ELEMS];          // lo
__device__ __nv_bfloat16 g_cw1h[9*64*64];            // [tap][co][ci] bf16 hi, BN-folded
__device__ __nv_bfloat16 g_cw1l[9*64*64];
__device__ __nv_bfloat16 g_cw2h[9*64*64];
__device__ __nv_bfloat16 g_cw2l[9*64*64];
__device__ __nv_bfloat16 g_mw1h[2*64*64];            // MLP L1 W [panel][co][k] hi (k<128)
__device__ __nv_bfloat16 g_mw1l[2*64*64];
__device__ __nv_bfloat16 g_mw2h[64*64];              // MLP L2 W [co][c]
__device__ __nv_bfloat16 g_mw2l[64*64];
__device__ float g_w1p[3*64];                        // pos rows of W1 (BN-folded, fp32)
__device__ float g_fb1[64];
__device__ float g_cb1[64];
__device__ float g_cb2[64];

// ---------------- mma / ldmatrix / cp.async helpers ----------------
__device__ __forceinline__ uint32_t smem_u32(const void* p){
    uint32_t a;
    asm("{ .reg .u64 t; cvta.to.shared.u64 t, %1; cvt.u32.u64 %0, t; }"
        : "=r"(a) : "l"(p));
    return a;
}
#define LDSM_X4(r0,r1,r2,r3,addr) asm volatile( \
    "ldmatrix.sync.aligned.m8n8.x4.shared.b16 {%0,%1,%2,%3}, [%4];" \
    : "=r"(r0), "=r"(r1), "=r"(r2), "=r"(r3) : "r"(addr))
#define LDSM_X2(r0,r1,addr) asm volatile( \
    "ldmatrix.sync.aligned.m8n8.x2.shared.b16 {%0,%1}, [%2];" \
    : "=r"(r0), "=r"(r1) : "r"(addr))
#define MMA_BF16(c0,c1,c2,c3,a0,a1,a2,a3,b0,b1) asm volatile( \
    "mma.sync.aligned.m16n8k16.row.col.f32.bf16.bf16.f32 " \
    "{%0,%1,%2,%3}, {%4,%5,%6,%7}, {%8,%9}, {%0,%1,%2,%3};" \
    : "+f"(c0), "+f"(c1), "+f"(c2), "+f"(c3) \
    : "r"(a0), "r"(a1), "r"(a2), "r"(a3), "r"(b0), "r"(b1))
#define CP16(dst, src) asm volatile( \
    "cp.async.cg.shared.global [%0], [%1], 16;" :: "r"(dst), "l"(src))
#define CP_COMMIT() asm volatile("cp.async.commit_group;" ::: "memory")
#define CP_WAIT(n)  asm volatile("cp.async.wait_group %0;" :: "n"(n) : "memory")

// bf16x2 hi/lo split of two fp32 values (rn residual split)
__device__ __forceinline__ void split2(float v0, float v1,
                                       uint32_t& hp, uint32_t& lp){
    __nv_bfloat16 h0 = __float2bfloat16(v0);
    __nv_bfloat16 h1 = __float2bfloat16(v1);
    __nv_bfloat16 l0 = __float2bfloat16(v0 - __bfloat162float(h0));
    __nv_bfloat16 l1 = __float2bfloat16(v1 - __bfloat162float(h1));
    hp = (uint32_t)__bfloat16_as_ushort(h0) |
         ((uint32_t)__bfloat16_as_ushort(h1) << 16);
    lp = (uint32_t)__bfloat16_as_ushort(l0) |
         ((uint32_t)__bfloat16_as_ushort(l1) << 16);
}

// ---------------- init: zero BEV grid + fold weights (one launch) ----------------
#define ZBLOCKS 16641    // ceil(GRID_ELEMS/4 / 256)
#define PREP_TOTAL (8192 + 4096 + 192 + 64 + 2*9*64*64 + 2*64)

__global__ void init_kernel(
    const float* __restrict__ w1, const float* __restrict__ b1,
    const float* __restrict__ g1, const float* __restrict__ be1,
    const float* __restrict__ m1, const float* __restrict__ v1,
    const float* __restrict__ w2,
    const float* __restrict__ cw1, const float* __restrict__ cb1,
    const float* __restrict__ cg1, const float* __restrict__ cbe1,
    const float* __restrict__ cm1, const float* __restrict__ cv1,
    const float* __restrict__ cw2, const float* __restrict__ cb2,
    const float* __restrict__ cg2, const float* __restrict__ cbe2,
    const float* __restrict__ cm2, const float* __restrict__ cv2)
{
    if (blockIdx.x < ZBLOCKS){
        size_t i = (size_t)blockIdx.x*256 + threadIdx.x;
        if (i < GRID_ELEMS/4)
            ((float4*)g_bev)[i] = make_float4(0.f,0.f,0.f,0.f);
        return;
    }
    int idx = (blockIdx.x - ZBLOCKS)*256 + threadIdx.x;
    if (idx >= PREP_TOTAL) return;
    if (idx < 8192){                      // MLP W1 k<128: [panel][co][kk]
        int p = idx >> 12, r = idx & 4095, co = r >> 6, kk = r & 63;
        int k = p*64 + kk;
        float s = g1[co]*rsqrtf(v1[co]+1e-5f);
        float wf = w1[k*64+co]*s;
        __nv_bfloat16 hi = __float2bfloat16(wf);
        g_mw1h[idx] = hi;
        g_mw1l[idx] = __float2bfloat16(wf - __bfloat162float(hi));
        return;
    }
    idx -= 8192;
    if (idx < 4096){                      // MLP W2: [co][c]
        int co = idx >> 6, c = idx & 63;
        float wf = w2[c*64+co];
        __nv_bfloat16 hi = __float2bfloat16(wf);
        g_mw2h[idx] = hi;
        g_mw2l[idx] = __float2bfloat16(wf - __bfloat162float(hi));
        return;
    }
    idx -= 4096;
    if (idx < 192){                       // pos rows of W1, fp32
        int i = idx >> 6, co = idx & 63;
        float s = g1[co]*rsqrtf(v1[co]+1e-5f);
        g_w1p[idx] = w1[(128+i)*64+co]*s;
        return;
    }
    idx -= 192;
    if (idx < 64){
        float s = g1[idx]*rsqrtf(v1[idx]+1e-5f);
        g_fb1[idx] = (b1[idx]-m1[idx])*s + be1[idx];
        return;
    }
    idx -= 64;
    if (idx < 9*64*64){
        int t = idx >> 12, co = (idx >> 6) & 63, ci = idx & 63;
        float s = cg1[co]*rsqrtf(cv1[co]+1e-5f);
        float wf = cw1[(co*64+ci)*9 + t]*s;
        __nv_bfloat16 hi = __float2bfloat16(wf);
        g_cw1h[idx] = hi;
        g_cw1l[idx] = __float2bfloat16(wf - __bfloat162float(hi));
        return;
    }
    idx -= 9*64*64;
    if (idx < 9*64*64){
        int t = idx >> 12, co = (idx >> 6) & 63, ci = idx & 63;
        float s = cg2[co]*rsqrtf(cv2[co]+1e-5f);
        float wf = cw2[(co*64+ci)*9 + t]*s;
        __nv_bfloat16 hi = __float2bfloat16(wf);
        g_cw2h[idx] = hi;
        g_cw2l[idx] = __float2bfloat16(wf - __bfloat162float(hi));
        return;
    }
    idx -= 9*64*64;
    if (idx < 64){
        float s = cg1[idx]*rsqrtf(cv1[idx]+1e-5f);
        g_cb1[idx] = (cb1[idx]-cm1[idx])*s + cbe1[idx];
        return;
    }
    idx -= 64;
    if (idx < 64){
        float s = cg2[idx]*rsqrtf(cv2[idx]+1e-5f);
        g_cb2[idx] = (cb2[idx]-cm2[idx])*s + cbe2[idx];
    }
}

// ---------------- tensor-core MLP + scatter-max (R13, proven) ----------------
#define MLPS_W1   0
#define MLPS_W2   32768
#define MLPS_A    49152
#define MLPS_HH   81920
#define MLPS_HL   90112
#define MLPS_W1P  98304
#define MLPS_FB1  99072
#define MLPS_B2   99328
#define MLPS_POS  99584      // 2 x 64 x 4 floats
#define MLPS_INFO 101632     // 2 x 64 ints
#define MLP_SMEM_BYTES 102144
#define NCHUNKS 6250

__global__ __launch_bounds__(256, 2)
void mlp_mma_kernel(const float* __restrict__ points,
                    const float* __restrict__ features,
                    const float* __restrict__ b2)
{
    extern __shared__ char smem[];
    uint32_t sb = smem_u32(smem);
    float* s_w1p = (float*)(smem + MLPS_W1P);
    float* s_fb1 = (float*)(smem + MLPS_FB1);
    float* s_b2  = (float*)(smem + MLPS_B2);

    int tid = threadIdx.x;
    int lane = tid & 31;
    int wq = tid >> 5;
    int wm = wq & 3;
    int wn = wq >> 2;
    int tile = lane >> 3;
    int r16  = ((tile & 1) << 3) + (lane & 7);
    int kcA  = tile >> 1;
    int coL  = lane & 7;
    int kcB  = tile & 1;

    for (int j = tid; j < 2048; j += 256){
        int panel = j >> 9, r = (j >> 3) & 63, c = j & 7;
        const __nv_bfloat16* src = (panel < 2)
            ? (g_mw1h + panel*4096 + r*64 + c*8)
            : (g_mw1l + (panel-2)*4096 + r*64 + c*8);
        CP16(sb + MLPS_W1 + panel*8192 + r*128 + ((c ^ (r & 7)) << 4), src);
    }
    for (int j = tid; j < 1024; j += 256){
        int panel = j >> 9, r = (j >> 3) & 63, c = j & 7;
        const __nv_bfloat16* src = (panel ? g_mw2l : g_mw2h) + r*64 + c*8;
        CP16(sb + MLPS_W2 + panel*8192 + r*128 + ((c ^ (r & 7)) << 4), src);
    }
    CP_COMMIT();
    if (tid < 192) s_w1p[tid] = g_w1p[tid];
    if (tid < 64){ s_fb1[tid] = g_fb1[tid]; s_b2[tid] = b2[tid]; }
    CP_WAIT(0);
    __syncthreads();

    int par = 0;
    for (int chunk = blockIdx.x; chunk < NCHUNKS; chunk += gridDim.x, par ^= 1){
        int g0 = chunk * 64;
        float* s_pos = (float*)(smem + MLPS_POS) + par*256;
        int*   s_info= (int*)(smem + MLPS_INFO) + par*64;

        // ---- stage A: issue ALL 8 feature loads first, then convert ----
        uint4 u[8];
        {
            #pragma unroll
            for (int i = 0; i < 4; ++i){
                int j = tid + i*256;
                int pt = j >> 4, oct = j & 15;
                const uint4* src =
                    (const uint4*)(features + (size_t)(g0+pt)*128 + oct*8);
                u[2*i]   = src[0];
                u[2*i+1] = src[1];
            }
            float px_ = 0.f, py_ = 0.f, pz_ = 0.f; int info = -1;
            if (tid < 64){
                int g = g0 + tid;
                float x = points[(size_t)g*3+0];
                float y = points[(size_t)g*3+1];
                float z = points[(size_t)g*3+2];
                bool valid = (x >= -50.f) && (x < 50.f) && (y >= -50.f) &&
                             (y < 50.f) && (z >= -3.f) && (z < 5.f);
                px_ = __fdiv_rn(x + 50.f, 100.f);
                py_ = __fdiv_rn(y + 50.f, 100.f);
                pz_ = __fdiv_rn(z + 3.f, 8.f);
                if (valid){
                    int col = (int)__fdiv_rn(x + 50.f, 0.390625f);
                    int row = (int)__fdiv_rn(y + 50.f, 0.390625f);
                    col = min(max(col,0),255); row = min(max(row,0),255);
                    int b = g / NPTS;
                    info = (b<<18) | (row<<9) | col;
                }
            }
            #pragma unroll
            for (int i = 0; i < 4; ++i){
                int j = tid + i*256;
                int pt = j >> 4, oct = j & 15;
                uint4 u0 = u[2*i], u1 = u[2*i+1];
                uint4 hv, lv;
                hv.x = __byte_perm(u0.x, u0.y, 0x7632);
                hv.y = __byte_perm(u0.z, u0.w, 0x7632);
                hv.z = __byte_perm(u1.x, u1.y, 0x7632);
                hv.w = __byte_perm(u1.z, u1.w, 0x7632);
                float l0 = __uint_as_float(u0.x) - __uint_as_float(u0.x & 0xFFFF0000u);
                float l1 = __uint_as_float(u0.y) - __uint_as_float(u0.y & 0xFFFF0000u);
                float l2 = __uint_as_float(u0.z) - __uint_as_float(u0.z & 0xFFFF0000u);
                float l3 = __uint_as_float(u0.w) - __uint_as_float(u0.w & 0xFFFF0000u);
                float l4 = __uint_as_float(u1.x) - __uint_as_float(u1.x & 0xFFFF0000u);
                float l5 = __uint_as_float(u1.y) - __uint_as_float(u1.y & 0xFFFF0000u);
                float l6 = __uint_as_float(u1.z) - __uint_as_float(u1.z & 0xFFFF0000u);
                float l7 = __uint_as_float(u1.w) - __uint_as_float(u1.w & 0xFFFF0000u);
                lv.x = __byte_perm(__float_as_uint(l0), __float_as_uint(l1), 0x7632);
                lv.y = __byte_perm(__float_as_uint(l2), __float_as_uint(l3), 0x7632);
                lv.z = __byte_perm(__float_as_uint(l4), __float_as_uint(l5), 0x7632);
                lv.w = __byte_perm(__float_as_uint(l6), __float_as_uint(l7), 0x7632);
                int panel = oct >> 3, c = oct & 7;
                uint32_t off = MLPS_A + panel*8192 + pt*128 + ((c ^ (pt & 7)) << 4);
                *(uint4*)(smem + off) = hv;
                *(uint4*)(smem + off + 16384) = lv;
            }
            if (tid < 64){
                s_pos[tid*4+0] = px_;
                s_pos[tid*4+1] = py_;
                s_pos[tid*4+2] = pz_;
                s_info[tid] = info;
            }
        }
        __syncthreads();                     // S1

        // ---- layer 1 GEMM ----
        float acc[4][4];
        #pragma unroll
        for (int in = 0; in < 4; ++in)
            #pragma unroll
            for (int r = 0; r < 4; ++r) acc[in][r] = 0.f;

        int arow = 16*wm + r16;
        #pragma unroll
        for (int ks = 0; ks < 8; ++ks){
            int panel = ks >> 2, cc = 2*(ks & 3);
            uint32_t ah[4], al[4], bh[4][2], bl[4][2];
            uint32_t aad = sb + MLPS_A + panel*8192 + arow*128
                         + (((cc + kcA) ^ (arow & 7)) << 4);
            LDSM_X4(ah[0], ah[1], ah[2], ah[3], aad);
            LDSM_X4(al[0], al[1], al[2], al[3], aad + 16384);
            #pragma unroll
            for (int in = 0; in < 4; ++in){
                int co = 32*wn + 8*in + coL;
                uint32_t bad = sb + MLPS_W1 + panel*8192 + co*128
                             + (((cc + kcB) ^ (co & 7)) << 4);
                LDSM_X2(bh[in][0], bh[in][1], bad);
                LDSM_X2(bl[in][0], bl[in][1], bad + 16384);
            }
            #pragma unroll
            for (int in = 0; in < 4; ++in){
                MMA_BF16(acc[in][0],acc[in][1],acc[in][2],acc[in][3],
                         ah[0],ah[1],ah[2],ah[3], bh[in][0],bh[in][1]);
                MMA_BF16(acc[in][0],acc[in][1],acc[in][2],acc[in][3],
                         ah[0],ah[1],ah[2],ah[3], bl[in][0],bl[in][1]);
                MMA_BF16(acc[in][0],acc[in][1],acc[in][2],acc[in][3],
                         al[0],al[1],al[2],al[3], bh[in][0],bh[in][1]);
            }
        }

        // ---- epilogue 1: + pos (fp32) + bias, ReLU, rn-split -> H ----
        int rb = 16*wm + (lane >> 2);
        int cb = 2*(lane & 3);
        #pragma unroll
        for (int in = 0; in < 4; ++in){
            int c0 = 32*wn + 8*in + cb;
            float p0a = s_w1p[c0],      p0b = s_w1p[c0+1];
            float p1a = s_w1p[64+c0],   p1b = s_w1p[64+c0+1];
            float p2a = s_w1p[128+c0],  p2b = s_w1p[128+c0+1];
            float fba = s_fb1[c0], fbb = s_fb1[c0+1];
            int ch = c0 >> 3;
            #pragma unroll
            for (int half = 0; half < 2; ++half){
                int pt = rb + 8*half;
                float px = s_pos[pt*4], py = s_pos[pt*4+1], pz = s_pos[pt*4+2];
                float v0 = acc[in][2*half]   + fba + px*p0a + py*p1a + pz*p2a;
                float v1 = acc[in][2*half+1] + fbb + px*p0b + py*p1b + pz*p2b;
                v0 = fmaxf(v0, 0.f); v1 = fmaxf(v1, 0.f);
                uint32_t hp, lp;
                split2(v0, v1, hp, lp);
                uint32_t off = pt*128 + ((ch ^ (pt & 7)) << 4) + cb*2;
                *(uint32_t*)(smem + MLPS_HH + off) = hp;
                *(uint32_t*)(smem + MLPS_HL + off) = lp;
            }
        }
        __syncthreads();                     // S2

        // ---- layer 2 GEMM ----
        float acc2[4][4];
        #pragma unroll
        for (int in = 0; in < 4; ++in)
            #pragma unroll
            for (int r = 0; r < 4; ++r) acc2[in][r] = 0.f;

        #pragma unroll
        for (int ks = 0; ks < 4; ++ks){
            int cc = 2*ks;
            uint32_t ah[4], al[4], bh[4][2], bl[4][2];
            uint32_t aad = sb + MLPS_HH + arow*128
                         + (((cc + kcA) ^ (arow & 7)) << 4);
            LDSM_X4(ah[0], ah[1], ah[2], ah[3], aad);
            LDSM_X4(al[0], al[1], al[2], al[3], aad + 8192);
            #pragma unroll
            for (int in = 0; in < 4; ++in){
                int co = 32*wn + 8*in + coL;
                uint32_t bad = sb + MLPS_W2 + co*128
                             + (((cc + kcB) ^ (co & 7)) << 4);
                LDSM_X2(bh[in][0], bh[in][1], bad);
                LDSM_X2(bl[in][0], bl[in][1], bad + 8192);
            }
            #pragma unroll
            for (int in = 0; in < 4; ++in){
                MMA_BF16(acc2[in][0],acc2[in][1],acc2[in][2],acc2[in][3],
                         ah[0],ah[1],ah[2],ah[3], bh[in][0],bh[in][1]);
                MMA_BF16(acc2[in][0],acc2[in][1],acc2[in][2],acc2[in][3],
                         ah[0],ah[1],ah[2],ah[3], bl[in][0],bl[in][1]);
                MMA_BF16(acc2[in][0],acc2[in][1],acc2[in][2],acc2[in][3],
                         al[0],al[1],al[2],al[3], bh[in][0],bh[in][1]);
            }
        }

        // ---- epilogue 2: + b2, scatter-max (NHWC: adjacent channels) ----
        #pragma unroll
        for (int in = 0; in < 4; ++in){
            int c0 = 32*wn + 8*in + cb;
            float bb0 = s_b2[c0], bb1 = s_b2[c0+1];
            #pragma unroll
            for (int half = 0; half < 2; ++half){
                int pt = rb + 8*half;
                int info = s_info[pt];
                if (info < 0) continue;
                int b   = info >> 18;
                int row = (info >> 9) & 511;
                int col = info & 511;
                float v0 = acc2[in][2*half]   + bb0;
                float v1 = acc2[in][2*half+1] + bb1;
                size_t obase = (((size_t)b*HPAD + row + 1)*WPAD + col + 1)*64 + c0;
                if (v0 > 0.f)
                    atomicMax((unsigned int*)&g_bev[obase], __float_as_uint(v0));
                if (v1 > 0.f)
                    atomicMax((unsigned int*)&g_bev[obase + 1],
                              __float_as_uint(v1));
            }
        }
        // no end barrier: pos/info double-buffered; A/H protected by S1/S2
    }
}

// ---------------- tensor-core conv via mma.sync bf16 ----------------
// MODE 0: input = fp32 NHWC g_bev, staged via batched LDG + split2 + STS.
// MODE 1: input = bf16 hi/lo via cp.async. Out: MODE0 bf16 hi/lo, MODE1 fp32 NCHW.
#define SA_BUF   33280
#define SW_OFF   (2*SA_BUF)            // 66560
#define SW_BUF   16384
#define SBIAS    (SW_OFF + 2*SW_BUF)   // 99328
#define CONV_SMEM_BYTES (SBIAS + 256)  // 99584

template<int MODE>
__global__ __launch_bounds__(256, 2)
void conv_mma_kernel(const float* __restrict__ in_f,
                     const __nv_bfloat16* __restrict__ in_h,
                     const __nv_bfloat16* __restrict__ in_l,
                     const __nv_bfloat16* __restrict__ w_h,
                     const __nv_bfloat16* __restrict__ w_l,
                     const float* __restrict__ bias,
                     __nv_bfloat16* __restrict__ out_h,
                     __nv_bfloat16* __restrict__ out_l,
                     float* __restrict__ out_f)
{
    extern __shared__ char smem[];
    uint32_t sbase = smem_u32(smem);
    float* s_bias = (float*)(smem + SBIAS);

    int tid = threadIdx.x;
    int lane = tid & 31;
    int wq = tid >> 5;
    int wm = wq & 3;
    int wn = wq >> 2;
    int b = blockIdx.z, h = blockIdx.y, W0 = blockIdx.x * 128;

    if (tid < 64) s_bias[tid] = bias[tid];

    int tile = lane >> 3;
    int r16  = ((tile & 1) << 3) + (lane & 7);
    int kcA  = tile >> 1;
    int coL  = (lane & 7);
    int kcB  = tile & 1;

    // MODE 1: cp.async strip staging (bf16 hi/lo inputs)
    auto stage_strip_async = [&](int dh, int buf){
        const char* srch = (const char*)(in_h +
            (((size_t)b*HPAD + h + dh)*WPAD + W0)*64);
        const char* srcl = (const char*)(in_l +
            (((size_t)b*HPAD + h + dh)*WPAD + W0)*64);
        uint32_t dsth = sbase + buf*SA_BUF;
        uint32_t dstl = dsth + 16640;
        #pragma unroll 1
        for (int ch = tid; ch < 1040; ch += 256){
            int px = ch >> 3, c = ch & 7;
            uint32_t off = px*128 + ((c ^ (px & 7)) << 4);
            CP16(dsth + off, srch + ch*16);
            CP16(dstl + off, srcl + ch*16);
        }
    };
    // MODE 0: batched LDG fp32 (all loads first) -> split2 -> STS
    auto stage_strip_f32 = [&](int dh, int buf){
        const float* src = in_f + (((size_t)b*HPAD + h + dh)*WPAD + W0)*64;
        char* dsth = smem + buf*SA_BUF;
        char* dstl = dsth + 16640;
        float4 f[10];
        #pragma unroll
        for (int it = 0; it < 5; ++it){
            int ch = tid + it*256;
            if (ch < 1040){
                const float4* s4 = (const float4*)(src + (ch>>3)*64 + (ch&7)*8);
                f[2*it]   = s4[0];
                f[2*it+1] = s4[1];
            }
        }
        #pragma unroll
        for (int it = 0; it < 5; ++it){
            int ch = tid + it*256;
            if (ch < 1040){
                int px = ch >> 3, c = ch & 7;
                uint4 hv, lv;
                split2(f[2*it].x,   f[2*it].y,   hv.x, lv.x);
                split2(f[2*it].z,   f[2*it].w,   hv.y, lv.y);
                split2(f[2*it+1].x, f[2*it+1].y, hv.z, lv.z);
                split2(f[2*it+1].z, f[2*it+1].w, hv.w, lv.w);
                uint32_t off = px*128 + ((c ^ (px & 7)) << 4);
                *(uint4*)(dsth + off) = hv;
                *(uint4*)(dstl + off) = lv;
            }
        }
    };
    auto stage_strip = [&](int dh, int buf){
        if (MODE == 0) stage_strip_f32(dh, buf);
        else           stage_strip_async(dh, buf);
    };
    auto stage_w = [&](int t, int buf){
        const char* srch = (const char*)(w_h + t*4096);
        const char* srcl = (const char*)(w_l + t*4096);
        uint32_t dsth = sbase + SW_OFF + buf*SW_BUF;
        uint32_t dstl = dsth + 8192;
        #pragma unroll 1
        for (int ch = tid; ch < 512; ch += 256){
            int co = ch >> 3, c = ch & 7;
            uint32_t off = co*128 + ((c ^ (co & 7)) << 4);
            CP16(dsth + off, srch + ch*16);
            CP16(dstl + off, srcl + ch*16);
        }
    };

    float acc[2][4][4];
    #pragma unroll
    for (int im = 0; im < 2; ++im)
        #pragma unroll
        for (int in = 0; in < 4; ++in)
            #pragma unroll
            for (int r = 0; r < 4; ++r) acc[im][in][r] = 0.f;

    stage_w(0, 0);
    stage_strip(0, 0);
    CP_COMMIT();

    #pragma unroll 1
    for (int t = 0; t < 9; ++t){
        int dh = t / 3, dw = t - dh*3;
        if (t < 8){
            stage_w(t+1, (t+1) & 1);
            if ((t+1) % 3 == 0) stage_strip((t+1)/3, ((t+1)/3) & 1);
            CP_COMMIT();
            CP_WAIT(1);
        } else {
            CP_WAIT(0);
        }
        __syncthreads();

        uint32_t Ah = sbase + (dh & 1)*SA_BUF;
        uint32_t Al = Ah + 16640;
        uint32_t Wh = sbase + SW_OFF + (t & 1)*SW_BUF;
        uint32_t Wl = Wh + 8192;

        #pragma unroll
        for (int ks = 0; ks < 4; ++ks){
            uint32_t ah[2][4], al[2][4], bh[4][2], bl[4][2];
            #pragma unroll
            for (int im = 0; im < 2; ++im){
                int px = dw + 32*wm + 16*im + r16;
                int chunk = 2*ks + kcA;
                uint32_t ad = Ah + px*128 + ((chunk ^ (px & 7)) << 4);
                LDSM_X4(ah[im][0], ah[im][1], ah[im][2], ah[im][3], ad);
            }
            #pragma unroll
            for (int in = 0; in < 4; ++in){
                int co = 32*wn + 8*in + coL;
                int chunk = 2*ks + kcB;
                uint32_t bd = Wh + co*128 + ((chunk ^ (co & 7)) << 4);
                LDSM_X2(bh[in][0], bh[in][1], bd);
            }
            #pragma unroll
            for (int im = 0; im < 2; ++im)
                #pragma unroll
                for (int in = 0; in < 4; ++in)
                    MMA_BF16(acc[im][in][0], acc[im][in][1],
                             acc[im][in][2], acc[im][in][3],
                             ah[im][0], ah[im][1], ah[im][2], ah[im][3],
                             bh[in][0], bh[in][1]);
            #pragma unroll
            for (int in = 0; in < 4; ++in){
                int co = 32*wn + 8*in + coL;
                int chunk = 2*ks + kcB;
                uint32_t bd = Wl + co*128 + ((chunk ^ (co & 7)) << 4);
                LDSM_X2(bl[in][0], bl[in][1], bd);
            }
            #pragma unroll
            for (int im = 0; im < 2; ++im)
                #pragma unroll
                for (int in = 0; in < 4; ++in)
                    MMA_BF16(acc[im][in][0], acc[im][in][1],
                             acc[im][in][2], acc[im][in][3],
                             ah[im][0], ah[im][1], ah[im][2], ah[im][3],
                             bl[in][0], bl[in][1]);
            #pragma unroll
            for (int im = 0; im < 2; ++im){
                int px = dw + 32*wm + 16*im + r16;
                int chunk = 2*ks + kcA;
                uint32_t ad = Al + px*128 + ((chunk ^ (px & 7)) << 4);
                LDSM_X4(al[im][0], al[im][1], al[im][2], al[im][3], ad);
            }
            #pragma unroll
            for (int im = 0; im < 2; ++im)
                #pragma unroll
                for (int in = 0; in < 4; ++in)
                    MMA_BF16(acc[im][in][0], acc[im][in][1],
                             acc[im][in][2], acc[im][in][3],
                             al[im][0], al[im][1], al[im][2], al[im][3],
                             bh[in][0], bh[in][1]);
        }
        __syncthreads();
    }

    int rbase = 32*wm + (lane >> 2);
    int cbase = 32*wn + 2*(lane & 3);
    #pragma unroll
    for (int im = 0; im < 2; ++im){
        #pragma unroll
        for (int in = 0; in < 4; ++in){
            int c0 = cbase + 8*in;
            float bia = s_bias[c0], bib = s_bias[c0+1];
            #pragma unroll
            for (int half = 0; half < 2; ++half){
                int px = rbase + 16*im + 8*half;
                float v0 = fmaxf(acc[im][in][2*half]   + bia, 0.f);
                float v1 = fmaxf(acc[im][in][2*half+1] + bib, 0.f);
                if (MODE == 0){
                    uint32_t hp, lp;
                    split2(v0, v1, hp, lp);
                    size_t e = (((size_t)b*HPAD + h + 1)*WPAD + (W0 + px + 1))*64 + c0;
                    *(uint32_t*)(out_h + e) = hp;
                    *(uint32_t*)(out_l + e) = lp;
                } else {
                    size_t e = ((size_t)(b*64 + c0)*HN + h)*WN + W0 + px;
                    out_f[e] = v0;
                    out_f[e + (size_t)HN*WN] = v1;
                }
            }
        }
    }
}

// ---------------- launch ----------------
extern "C" void kernel_launch(void* const* d_in, const int* in_sizes, int n_in,
                              void* d_out, int out_size)
{
    const float* points   = (const float*)d_in[0];
    const float* features = (const float*)d_in[1];
    const float* w1   = (const float*)d_in[2];
    const float* b1   = (const float*)d_in[3];
    const float* g1   = (const float*)d_in[4];
    const float* be1  = (const float*)d_in[5];
    const float* m1   = (const float*)d_in[6];
    const float* v1   = (const float*)d_in[7];
    const float* w2   = (const float*)d_in[8];
    const float* b2   = (const float*)d_in[9];
    const float* cw1  = (const float*)d_in[10];
    const float* cb1  = (const float*)d_in[11];
    const float* cg1  = (const float*)d_in[12];
    const float* cbe1 = (const float*)d_in[13];
    const float* cm1  = (const float*)d_in[14];
    const float* cv1  = (const float*)d_in[15];
    const float* cw2  = (const float*)d_in[16];
    const float* cb2  = (const float*)d_in[17];
    const float* cg2  = (const float*)d_in[18];
    const float* cbe2 = (const float*)d_in[19];
    const float* cm2  = (const float*)d_in[20];
    const float* cv2  = (const float*)d_in[21];
    float* out = (float*)d_out;

    void *p_bev, *p_c2h, *p_c2l;
    void *p_w1h, *p_w1l, *p_w2h, *p_w2l, *p_cb1, *p_cb2;
    cudaGetSymbolAddress(&p_bev, g_bev);
    cudaGetSymbolAddress(&p_c2h, g_c2h);
    cudaGetSymbolAddress(&p_c2l, g_c2l);
    cudaGetSymbolAddress(&p_w1h, g_cw1h);
    cudaGetSymbolAddress(&p_w1l, g_cw1l);
    cudaGetSymbolAddress(&p_w2h, g_cw2h);
    cudaGetSymbolAddress(&p_w2l, g_cw2l);
    cudaGetSymbolAddress(&p_cb1, g_cb1);
    cudaGetSymbolAddress(&p_cb2, g_cb2);

    cudaFuncSetAttribute(mlp_mma_kernel,
        cudaFuncAttributeMaxDynamicSharedMemorySize, MLP_SMEM_BYTES);
    cudaFuncSetAttribute(conv_mma_kernel<0>,
        cudaFuncAttributeMaxDynamicSharedMemorySize, CONV_SMEM_BYTES);
    cudaFuncSetAttribute(conv_mma_kernel<1>,
        cudaFuncAttributeMaxDynamicSharedMemorySize, CONV_SMEM_BYTES);

    // 1) zero BEV grid + fold weights (one launch)
    int prep_blocks = (PREP_TOTAL + 255)/256;
    init_kernel<<<ZBLOCKS + prep_blocks, 256>>>(
        w1,b1,g1,be1,m1,v1, w2,
        cw1,cb1,cg1,cbe1,cm1,cv1,
        cw2,cb2,cg2,cbe2,cm2,cv2);

    // 2) tensor-core point MLP + scatter-max (persistent, NHWC scatter)
    mlp_mma_kernel<<<296, 256, MLP_SMEM_BYTES>>>(points, features, b2);

    // 3) conv1 (mma.sync): fp32 g_bev -> g_c2 hi/lo (batched inline split)
    dim3 cgrid(2, HN, BATCH);
    conv_mma_kernel<0><<<cgrid, 256, CONV_SMEM_BYTES>>>(
        (const float*)p_bev, nullptr, nullptr,
        (const __nv_bfloat16*)p_w1h, (const __nv_bfloat16*)p_w1l,
        (const float*)p_cb1,
        (__nv_bfloat16*)p_c2h, (__nv_bfloat16*)p_c2l, nullptr);

    // 4) conv2 (mma.sync): g_c2 hi/lo -> d_out (NCHW fp32)
    conv_mma_kernel<1><<<cgrid, 256, CONV_SMEM_BYTES>>>(
        nullptr,
        (const __nv_bfloat16*)p_c2h, (const __nv_bfloat16*)p_c2l,
        (const __nv_bfloat16*)p_w2h, (const __nv_bfloat16*)p_w2l,
        (const float*)p_cb2,
        nullptr, nullptr, out);
}